// round 2
// baseline (speedup 1.0000x reference)
#include <cuda_runtime.h>
#include <cstdint>
#include <cstddef>

#define Tn 1024
#define Bn 512
#define Hn 128
#define In 64
#define G3 384

// 805 MB scratch for precomputed input-side gate projections: xg[b][t][g]
__device__ float g_xg[(size_t)Bn * Tn * G3];

// ---------------------------------------------------------------------------
// Packed f32x2 FMA (Blackwell): d.lo += a.lo*b.lo ; d.hi += a.hi*b.hi
// ---------------------------------------------------------------------------
__device__ __forceinline__ void ffma2(unsigned long long& d,
                                      const unsigned long long a,
                                      const unsigned long long b) {
    asm("fma.rn.f32x2 %0, %1, %2, %0;" : "+l"(d) : "l"(a), "l"(b));
}

__device__ __forceinline__ float hsum2(unsigned long long v) {
    float lo, hi;
    asm("mov.b64 {%0, %1}, %2;" : "=f"(lo), "=f"(hi) : "l"(v));
    return lo + hi;
}

__device__ __forceinline__ float sigf(float x) {
    return __fdividef(1.0f, 1.0f + __expf(-x));
}
__device__ __forceinline__ float tanh_fast(float x) {
    return 1.0f - __fdividef(2.0f, 1.0f + __expf(2.0f * x));
}

// ---------------------------------------------------------------------------
// Kernel 1: xg[r][g] = x[r][:] . W_ih[g][:] + b_ih[g] + (g<256 ? b_hh[g] : 0)
// r = b*T + t, R = 524288 rows. Tiles: 128 rows x 96 cols, 256 threads,
// thread tile 8 rows x 6 cols. Dynamic smem (58.1 KB > 48 KB static cap).
// ---------------------------------------------------------------------------
#define XG_SMEM_FLOATS (128 * 64 + 96 * 68)
#define XG_SMEM_BYTES  (XG_SMEM_FLOATS * 4)

__global__ void __launch_bounds__(256, 1)
xg_gemm(const float* __restrict__ x,
        const float* __restrict__ Wih,
        const float* __restrict__ bih,
        const float* __restrict__ bhh) {
    extern __shared__ float smg[];
    float* xs = smg;                 // [128][64]
    float* ws = smg + 128 * 64;      // [96][68] padded

    const int tid = threadIdx.x;
    const int r0 = blockIdx.x * 128;
    const int cb = blockIdx.y;       // 0..3 -> 96 gate-cols each

    // Load X tile (coalesced float4)
    {
        const float4* xg4 = (const float4*)(x + (size_t)r0 * 64);
        float4* xs4 = (float4*)xs;
        #pragma unroll
        for (int i = tid; i < 128 * 16; i += 256) xs4[i] = xg4[i];
    }
    // Load W tile into padded layout
    {
        const float4* wg4 = (const float4*)(Wih + (size_t)cb * 96 * 64);
        #pragma unroll
        for (int i = tid; i < 96 * 16; i += 256) {
            int g = i >> 4, k4 = i & 15;
            *(float4*)(ws + g * 68 + k4 * 4) = wg4[i];
        }
    }
    __syncthreads();

    const int ry = tid >> 4;   // 0..15 -> rows ry*8 .. +8
    const int cx = tid & 15;   // cols cx + 16*jj

    unsigned long long acc[8][6];
    #pragma unroll
    for (int i = 0; i < 8; i++)
        #pragma unroll
        for (int jj = 0; jj < 6; jj++) acc[i][jj] = 0ULL;

    #pragma unroll
    for (int k4 = 0; k4 < 16; k4++) {
        ulonglong2 wv[6];
        #pragma unroll
        for (int jj = 0; jj < 6; jj++)
            wv[jj] = *(const ulonglong2*)(ws + (cx + 16 * jj) * 68 + k4 * 4);
        #pragma unroll
        for (int i = 0; i < 8; i++) {
            ulonglong2 xv = *(const ulonglong2*)(xs + (ry * 8 + i) * 64 + k4 * 4);
            #pragma unroll
            for (int jj = 0; jj < 6; jj++) {
                ffma2(acc[i][jj], xv.x, wv[jj].x);
                ffma2(acc[i][jj], xv.y, wv[jj].y);
            }
        }
    }

    // Epilogue: horizontal add + biases, write scratch
    #pragma unroll
    for (int jj = 0; jj < 6; jj++) {
        const int g = cb * 96 + cx + 16 * jj;
        const float bias = bih[g] + (g < 256 ? bhh[g] : 0.0f);
        #pragma unroll
        for (int i = 0; i < 8; i++) {
            const int r = r0 + ry * 8 + i;
            g_xg[(size_t)r * G3 + g] = hsum2(acc[i][jj]) + bias;
        }
    }
}

// ---------------------------------------------------------------------------
// Kernel 2: GRU recurrence + final FC. 128 blocks x 4 batches, 256 threads.
// Thread (j = tid&127, half = tid>>7): gate rows {j, j+128, j+256}, k-half.
// W_hh in smem [384][132] (pad -> conflict-free LDS.128). h broadcast.
// ---------------------------------------------------------------------------
#define SMEM_FLOATS (384 * 132 + 4 * 128 + 4 * 3 * 128)
#define SMEM_BYTES  (SMEM_FLOATS * 4)

__global__ void __launch_bounds__(256, 1)
gru_kernel(const float* __restrict__ Whh,
           const float* __restrict__ bhh,
           const float* __restrict__ Wfc,
           const float* __restrict__ bfc,
           float* __restrict__ out) {
    extern __shared__ float sm[];
    float* Wsh = sm;                    // [384][132]
    float* hsh = sm + 384 * 132;        // [4][128]
    float* red = hsh + 4 * 128;         // [4][3][128] partials from half 1

    const int tid = threadIdx.x;
    const int j = tid & 127;
    const int half = tid >> 7;
    const int b0 = blockIdx.x * 4;

    // Load W_hh into padded smem (float4, coalesced)
    #pragma unroll
    for (int i = tid; i < 384 * 32; i += 256) {
        int g = i >> 5, k4 = i & 31;
        *(float4*)(Wsh + g * 132 + k4 * 4) = ((const float4*)Whh)[i];
    }
    for (int i = tid; i < 512; i += 256) hsh[i] = 0.0f;

    float hreg[4] = {0.f, 0.f, 0.f, 0.f};
    const float bn = bhh[256 + j];   // n-gate hidden bias (inside r*(...))
    __syncthreads();

    const ulonglong2* Wr = (const ulonglong2*)(Wsh + j * 132 + half * 64);
    const ulonglong2* Wz = (const ulonglong2*)(Wsh + (j + 128) * 132 + half * 64);
    const ulonglong2* Wn = (const ulonglong2*)(Wsh + (j + 256) * 132 + half * 64);
    const ulonglong2* H0 = (const ulonglong2*)(hsh + half * 64);

    for (int t = 0; t < Tn; t++) {
        // Prefetch this step's input-side projections (hidden under dot loop)
        float xr[4], xz[4], xn[4];
        if (half == 0) {
            #pragma unroll
            for (int b = 0; b < 4; b++) {
                const float* p = g_xg + ((size_t)(b0 + b) * Tn + t) * G3 + j;
                xr[b] = p[0];
                xz[b] = p[128];
                xn[b] = p[256];
            }
        }

        unsigned long long acc[3][4];
        #pragma unroll
        for (int g = 0; g < 3; g++)
            #pragma unroll
            for (int b = 0; b < 4; b++) acc[g][b] = 0ULL;

        #pragma unroll
        for (int kk = 0; kk < 16; kk++) {
            ulonglong2 wr = Wr[kk], wz = Wz[kk], wn = Wn[kk];
            #pragma unroll
            for (int b = 0; b < 4; b++) {
                ulonglong2 hv = H0[b * 32 + kk];   // broadcast
                ffma2(acc[0][b], wr.x, hv.x); ffma2(acc[0][b], wr.y, hv.y);
                ffma2(acc[1][b], wz.x, hv.x); ffma2(acc[1][b], wz.y, hv.y);
                ffma2(acc[2][b], wn.x, hv.x); ffma2(acc[2][b], wn.y, hv.y);
            }
        }

        if (half == 1) {
            #pragma unroll
            for (int b = 0; b < 4; b++) {
                red[(b * 3 + 0) * 128 + j] = hsum2(acc[0][b]);
                red[(b * 3 + 1) * 128 + j] = hsum2(acc[1][b]);
                red[(b * 3 + 2) * 128 + j] = hsum2(acc[2][b]);
            }
        }
        __syncthreads();

        if (half == 0) {
            #pragma unroll
            for (int b = 0; b < 4; b++) {
                float hr = hsum2(acc[0][b]) + red[(b * 3 + 0) * 128 + j];
                float hz = hsum2(acc[1][b]) + red[(b * 3 + 1) * 128 + j];
                float hn = hsum2(acc[2][b]) + red[(b * 3 + 2) * 128 + j] + bn;
                float r = sigf(xr[b] + hr);
                float z = sigf(xz[b] + hz);
                float n = tanh_fast(fmaf(r, hn, xn[b]));
                float h = hreg[b];
                float hnew = fmaf(z, h - n, n);   // (1-z)*n + z*h
                hreg[b] = hnew;
                hsh[b * 128 + j] = hnew;
            }
        }
        __syncthreads();
    }

    // Final FC: out[b][o] = h_T[b] . W_fc[o] + b_fc[o]
    if (tid < 4 * 51) {
        const int b = tid / 51, o = tid % 51;
        float a = bfc[o];
        const float* wf = Wfc + o * 128;
        const float* hp = hsh + b * 128;
        #pragma unroll 8
        for (int k = 0; k < 128; k++) a = fmaf(hp[k], wf[k], a);
        out[(b0 + b) * 51 + o] = a;
    }
}

// ---------------------------------------------------------------------------
// Launch
// ---------------------------------------------------------------------------
extern "C" void kernel_launch(void* const* d_in, const int* in_sizes, int n_in,
                              void* d_out, int out_size) {
    const float* x    = (const float*)d_in[0];  // [512,1,1024,64]
    const float* Wih  = (const float*)d_in[1];  // [384,64]
    const float* Whh  = (const float*)d_in[2];  // [384,128]
    const float* bih  = (const float*)d_in[3];  // [384]
    const float* bhh  = (const float*)d_in[4];  // [384]
    const float* Wfc  = (const float*)d_in[5];  // [51,128]
    const float* bfc  = (const float*)d_in[6];  // [51]
    float* out = (float*)d_out;                 // [512,51]

    static int attr_done = 0;
    if (!attr_done) {
        cudaFuncSetAttribute(xg_gemm,
                             cudaFuncAttributeMaxDynamicSharedMemorySize,
                             XG_SMEM_BYTES);
        cudaFuncSetAttribute(gru_kernel,
                             cudaFuncAttributeMaxDynamicSharedMemorySize,
                             SMEM_BYTES);
        attr_done = 1;
    }

    xg_gemm<<<dim3((Bn * Tn) / 128, 4, 1), 256, XG_SMEM_BYTES>>>(x, Wih, bih, bhh);
    gru_kernel<<<128, 256, SMEM_BYTES>>>(Whh, bhh, Wfc, bfc, out);
}